// round 2
// baseline (speedup 1.0000x reference)
#include <cuda_runtime.h>
#include <math.h>
#include <stdint.h>

#define B_    16
#define T_    1000
#define INDIM 257
#define FEAT  771
#define H_    512
#define KN    9
#define KS    6
#define M_    (B_*T_)        /* 16000 rows, time-major: row = t*B + b */
#define H3    (3*H_)         /* 1536 */
#define A2K   (H_*KN)        /* 4608 */
#define XT_LD 784            /* padded lda for FEAT=771 (16B-aligned rows) */
#define PLANE ((size_t)M_*H_)

// ---------------- scratch (device globals; no allocation allowed) ----------
__device__ float g_xT[(size_t)M_*XT_LD];   // inputs transposed to (t,b) rows
__device__ float g_h0[(size_t)M_*H_];      // tanh(input GEMM)
__device__ float g_U [(size_t)M_*H3];      // SRU pre-activations (reused L0/L1)
__device__ float g_h1[(size_t)M_*H_];
__device__ float g_h2[(size_t)M_*H_];
__device__ float g_y [(size_t)KN*M_*H_];   // conv+tanh, per-kn planes
__device__ float g_A2[(size_t)M_*A2K];     // pooled, feature = h*KN + kn

// ---------------- transpose (b,t,f) -> (t,b,f) -----------------------------
__global__ void transpose_kernel(const float* __restrict__ in, float* __restrict__ xT) {
    int row = blockIdx.x;                  // t*B + b
    int t = row >> 4, b = row & 15;
    const float* src = in + ((size_t)b*T_ + t)*FEAT;
    float* dst = xT + (size_t)row*XT_LD;
    for (int f = threadIdx.x; f < FEAT; f += blockDim.x) dst[f] = src[f];
}

// ---------------- generic SGEMM, 128x64x16 tile, fused epilogues -----------
// EPI 0: C = acc                      (SRU U)
// EPI 1: C = tanh(acc + bias[n])      (input layer)
// EPI 2: out = sigmoid(acc+bias[n]) * inputs[...,257+n], write center slice
template<int EPI>
__global__ __launch_bounds__(256, 2)
void sgemm_kernel(const float* __restrict__ A, int lda,
                  const float* __restrict__ Bm, int ldb,
                  float* __restrict__ C, int ldc,
                  int N, int K,
                  const float* __restrict__ bias,
                  const float* __restrict__ inp,
                  float* __restrict__ outp)
{
    const int BM = 128, BN = 64, BK = 16;
    __shared__ float As[BK][BM];
    __shared__ float Bs[BK][BN];

    int tid   = threadIdx.x;
    int mBase = blockIdx.y * BM;
    int nBase = blockIdx.x * BN;
    int tx = tid & 15;          // n dir (16 * TN=4 = 64)
    int ty = tid >> 4;          // m dir (16 * TM=8 = 128)

    int aRow = tid >> 2;        // 0..63
    int aCol = (tid & 3) * 4;   // 0,4,8,12
    int bRow = tid >> 4;        // 0..15
    int bCol = (tid & 15) * 4;  // 0..60

    float acc[8][4];
    #pragma unroll
    for (int i = 0; i < 8; i++)
        #pragma unroll
        for (int j = 0; j < 4; j++) acc[i][j] = 0.f;

    for (int k0 = 0; k0 < K; k0 += BK) {
        bool full = (k0 + BK <= K);
        // --- load A tile (128x16), store transposed As[k][m]
        #pragma unroll
        for (int r = 0; r < 2; r++) {
            size_t off = (size_t)(mBase + aRow + r*64)*lda + k0 + aCol;
            float v0, v1, v2, v3;
            if (full) {
                float4 v = *reinterpret_cast<const float4*>(A + off);
                v0 = v.x; v1 = v.y; v2 = v.z; v3 = v.w;
            } else {
                v0 = (k0+aCol+0 < K) ? A[off+0] : 0.f;
                v1 = (k0+aCol+1 < K) ? A[off+1] : 0.f;
                v2 = (k0+aCol+2 < K) ? A[off+2] : 0.f;
                v3 = (k0+aCol+3 < K) ? A[off+3] : 0.f;
            }
            As[aCol+0][aRow + r*64] = v0;
            As[aCol+1][aRow + r*64] = v1;
            As[aCol+2][aRow + r*64] = v2;
            As[aCol+3][aRow + r*64] = v3;
        }
        // --- load B tile (16x64), scalar loads (handles misaligned ldb/offset)
        {
            int k = k0 + bRow;
            float v0 = 0.f, v1 = 0.f, v2 = 0.f, v3 = 0.f;
            if (k < K) {
                size_t off = (size_t)k*ldb + nBase + bCol;
                int n = nBase + bCol;
                if (n + 3 < N) {
                    v0 = Bm[off+0]; v1 = Bm[off+1]; v2 = Bm[off+2]; v3 = Bm[off+3];
                } else {
                    if (n+0 < N) v0 = Bm[off+0];
                    if (n+1 < N) v1 = Bm[off+1];
                    if (n+2 < N) v2 = Bm[off+2];
                    if (n+3 < N) v3 = Bm[off+3];
                }
            }
            float4 v; v.x = v0; v.y = v1; v.z = v2; v.w = v3;
            *reinterpret_cast<float4*>(&Bs[bRow][bCol]) = v;
        }
        __syncthreads();

        #pragma unroll
        for (int kk = 0; kk < BK; kk++) {
            float a[8], b[4];
            *reinterpret_cast<float4*>(&a[0]) = *reinterpret_cast<const float4*>(&As[kk][ty*8]);
            *reinterpret_cast<float4*>(&a[4]) = *reinterpret_cast<const float4*>(&As[kk][ty*8+4]);
            *reinterpret_cast<float4*>(&b[0]) = *reinterpret_cast<const float4*>(&Bs[kk][tx*4]);
            #pragma unroll
            for (int i = 0; i < 8; i++)
                #pragma unroll
                for (int j = 0; j < 4; j++)
                    acc[i][j] = fmaf(a[i], b[j], acc[i][j]);
        }
        __syncthreads();
    }

    #pragma unroll
    for (int i = 0; i < 8; i++) {
        int m = mBase + ty*8 + i;
        if (EPI == 0) {
            // N is a multiple of 4 and <= actual N here; vector store
            float4 v;
            v.x = acc[i][0]; v.y = acc[i][1]; v.z = acc[i][2]; v.w = acc[i][3];
            *reinterpret_cast<float4*>(&C[(size_t)m*ldc + nBase + tx*4]) = v;
        } else {
            #pragma unroll
            for (int j = 0; j < 4; j++) {
                int n = nBase + tx*4 + j;
                if (n >= N) continue;
                float v = acc[i][j] + bias[n];
                if (EPI == 1) {
                    C[(size_t)m*ldc + n] = tanhf(v);
                } else {
                    float s = 1.f / (1.f + __expf(-v));
                    int b = m & 15, t = m >> 4;
                    size_t row = (size_t)b*T_ + t;
                    outp[row*INDIM + n] = s * inp[row*FEAT + INDIM + n];
                }
            }
        }
    }
}

// ---------------- SRU scan: one thread per (b,h), sequential over t --------
__global__ void scan_kernel(const float* __restrict__ U,
                            const float* __restrict__ X,
                            const float* __restrict__ v,
                            const float* __restrict__ bb,
                            float* __restrict__ Hout)
{
    int idx = blockIdx.x * blockDim.x + threadIdx.x;   // 0..B*H-1
    int b = idx / H_, h = idx % H_;
    float vf = v[h], vr = v[H_ + h];
    float bf = bb[h], br = bb[H_ + h];
    const float* Ub = U + (size_t)b*H3 + h;
    const float* Xb = X + (size_t)b*H_ + h;
    float*       Hb = Hout + (size_t)b*H_ + h;
    float c = 0.f;
    for (int t = 0; t < T_; t++) {
        size_t o3 = (size_t)t * (B_*H3);
        size_t o1 = (size_t)t * (B_*H_);
        float xt  = Ub[o3];
        float fp  = Ub[o3 + H_];
        float rp  = Ub[o3 + 2*H_];
        float xin = Xb[o1];
        float f = 1.f / (1.f + __expf(-(fmaf(vf, c, fp) + bf)));
        float cn = fmaf(f, c - xt, xt);
        float r = 1.f / (1.f + __expf(-(fmaf(vr, c, rp) + br)));
        Hb[o1] = fmaf(r, cn - xin, xin);
        c = cn;
    }
}

// ---------------- conv 6x6 (pad 3,2 / 3,2) + bias + tanh -------------------
__global__ void conv_kernel(const float* __restrict__ w, const float* __restrict__ cb,
                            const float* __restrict__ in, float* __restrict__ y)
{
    __shared__ float tile[13][40];        // (8+5) t-rows x (32+5) h-cols (pad->40)
    __shared__ float ws[KN][KS][KS];
    __shared__ float bs[KN];
    int b  = blockIdx.z;
    int t0 = blockIdx.y * 8;
    int h0 = blockIdx.x * 32;
    int tid = threadIdx.y * 32 + threadIdx.x;
    for (int i = tid; i < KN*KS*KS; i += 256) (&ws[0][0][0])[i] = w[i];
    if (tid < KN) bs[tid] = cb[tid];
    for (int i = tid; i < 13*37; i += 256) {
        int tr = i / 37, hc = i % 37;
        int t = t0 - 3 + tr, h = h0 - 3 + hc;
        float v = 0.f;
        if (t >= 0 && t < T_ && h >= 0 && h < H_)
            v = in[((size_t)t*B_ + b)*H_ + h];
        tile[tr][hc] = v;
    }
    __syncthreads();

    int ht = threadIdx.x, tt = threadIdx.y;
    float acc[KN];
    #pragma unroll
    for (int kn = 0; kn < KN; kn++) acc[kn] = 0.f;
    #pragma unroll
    for (int i = 0; i < KS; i++)
        #pragma unroll
        for (int j = 0; j < KS; j++) {
            float x = tile[tt + i][ht + j];
            #pragma unroll
            for (int kn = 0; kn < KN; kn++)
                acc[kn] = fmaf(ws[kn][i][j], x, acc[kn]);
        }
    size_t base = ((size_t)(t0 + tt)*B_ + b)*H_ + (h0 + ht);
    #pragma unroll
    for (int kn = 0; kn < KN; kn++)
        y[(size_t)kn*PLANE + base] = tanhf(acc[kn] + bs[kn]);
}

// ---------------- maxpool 3x3 stride 1 pad 1 + layout to (m, h*KN+kn) ------
__global__ void pool_kernel(const float* __restrict__ y, float* __restrict__ A2)
{
    size_t idx = (size_t)blockIdx.x * blockDim.x + threadIdx.x;  // (t*B+b)*H + h
    if (idx >= PLANE) return;
    int h = (int)(idx % H_);
    int t = (int)(idx / (H_*B_));
    size_t row = idx / H_;   // t*B + b
    int tlo = (t > 0) ? -1 : 0,  thi = (t < T_-1) ? 1 : 0;
    int hlo = (h > 0) ? -1 : 0,  hhi = (h < H_-1) ? 1 : 0;
    float* dst = A2 + row*A2K + (size_t)h*KN;
    #pragma unroll
    for (int kn = 0; kn < KN; kn++) {
        const float* p = y + (size_t)kn*PLANE + idx;
        float m = -3.0e38f;
        for (int dt = tlo; dt <= thi; dt++)
            for (int dh = hlo; dh <= hhi; dh++)
                m = fmaxf(m, p[(ptrdiff_t)dt*(B_*H_) + dh]);
        dst[kn] = m;
    }
}

// ---------------- driver ---------------------------------------------------
extern "C" void kernel_launch(void* const* d_in, const int* in_sizes, int n_in,
                              void* d_out, int out_size)
{
    const float* inputs = (const float*)d_in[0];
    const float* W_in   = (const float*)d_in[1];
    const float* b_in   = (const float*)d_in[2];
    const float* W_rnn  = (const float*)d_in[3];
    const float* v_rnn  = (const float*)d_in[4];
    const float* b_rnn  = (const float*)d_in[5];
    const float* conv_k = (const float*)d_in[6];
    const float* conv_b = (const float*)d_in[7];
    const float* W_out  = (const float*)d_in[8];
    const float* b_out  = (const float*)d_in[9];
    float* out = (float*)d_out;

    float *xT, *h0, *U, *h1, *h2, *y, *A2;
    cudaGetSymbolAddress((void**)&xT, g_xT);
    cudaGetSymbolAddress((void**)&h0, g_h0);
    cudaGetSymbolAddress((void**)&U,  g_U);
    cudaGetSymbolAddress((void**)&h1, g_h1);
    cudaGetSymbolAddress((void**)&h2, g_h2);
    cudaGetSymbolAddress((void**)&y,  g_y);
    cudaGetSymbolAddress((void**)&A2, g_A2);

    // 1. transpose inputs to time-major (padded rows for alignment)
    transpose_kernel<<<M_, 256>>>(inputs, xT);

    // 2. input layer: tanh(xT @ W_in + b_in) -> h0   (M=16000, N=512, K=771)
    sgemm_kernel<1><<<dim3(512/64, M_/128), 256>>>(
        xT, XT_LD, W_in, H_, h0, H_, H_, FEAT, b_in, nullptr, nullptr);

    // 3. SRU layer 0
    sgemm_kernel<0><<<dim3(H3/64, M_/128), 256>>>(
        h0, H_, W_rnn, H3, U, H3, H3, H_, nullptr, nullptr, nullptr);
    scan_kernel<<<(B_*H_)/256, 256>>>(U, h0, v_rnn, b_rnn, h1);

    // 4. SRU layer 1
    sgemm_kernel<0><<<dim3(H3/64, M_/128), 256>>>(
        h1, H_, W_rnn + (size_t)H_*H3, H3, U, H3, H3, H_, nullptr, nullptr, nullptr);
    scan_kernel<<<(B_*H_)/256, 256>>>(U, h1, v_rnn + 2*H_, b_rnn + 2*H_, h2);

    // 5. conv + tanh
    conv_kernel<<<dim3(H_/32, T_/8, B_), dim3(32, 8)>>>(conv_k, conv_b, h2, y);

    // 6. maxpool + repack to (m, h*KN+kn)
    pool_kernel<<<(unsigned)((PLANE + 255)/256), 256>>>(y, A2);

    // 7. output GEMM on the needed 257 columns only, fused sigmoid*input
    sgemm_kernel<2><<<dim3((INDIM + 63)/64, M_/128), 256>>>(
        A2, A2K, W_out + INDIM, FEAT, nullptr, 0, INDIM, A2K,
        b_out + INDIM, inputs, out);
}